// round 7
// baseline (speedup 1.0000x reference)
#include <cuda_runtime.h>

#define HH    1024
#define NST   64
#define LL    2048
#define NWARP 4
#define NPW   (NST / NWARP)   // 16 n per warp

// Accurate sincos for |x| <= ~110, independent of compiler fast-math flags.
__device__ __forceinline__ void my_sincos(float x, float* sp, float* cp) {
    float k = rintf(x * 0.63661977236f);           // x * 2/pi
    float r = fmaf(k, -1.57079637e+0f, x);         // x - k*PIO2_HI
    r = fmaf(k, 4.37113900e-8f, r);                // + k*PIO2_MID
    int q = ((int)k) & 3;
    float r2 = r * r;
    float s0 = fmaf(r2, -1.9515296e-4f, 8.3321609e-3f);
    s0 = fmaf(r2, s0, -1.6666655e-1f);
    float sr = fmaf(r * r2, s0, r);
    float c0 = fmaf(r2, 2.4433157e-5f, -1.3887316e-3f);
    c0 = fmaf(r2, c0, 4.1666646e-2f);
    c0 = fmaf(r2, c0, -0.5f);
    float cr = fmaf(r2, c0, 1.0f);
    float ss = (q & 1) ? cr : sr;
    float cc = (q & 1) ? sr : cr;
    if (q == 1 || q == 2) cc = -cc;
    if (q >= 2) ss = -ss;
    *sp = ss; *cp = cc;
}

// Single fused kernel. One CTA per h, 4 warps.
// Chirp factorization: l = j1 + 64*j2 (j1<64, j2<32):
//   K[h,l] = sum_n Re( W2[n,j2] * W1[n,j1] ),
//   W1[n,j1] = w_n^j1,  W2[n,j2] = Cm_n * (w_n^64)^j2   (2x folded into Cm).
// W1sh: [64 n][32 slots] float4 = (w^t, w^(t+32)), slot = t XOR (n&31). 32KB.
// W2sh: [16 p][64 n] float4 = (W2[n][2p], W2[n][2p+1]).  Broadcast reads at
//       base + n*16B + p*1024B  -> p-offsets are LDS immediates, zero ALU. 16KB.
// Lane t accumulates j1 = t (accA) and j1 = t+32 (accB) for all 32 j2.
__global__ void __launch_bounds__(32 * NWARP, 4) s4d_all(
        const float* __restrict__ A_real,
        const float* __restrict__ A_imag,
        const float* __restrict__ Bg,
        const float* __restrict__ Cg,
        const float* __restrict__ inv_dt,
        float* __restrict__ out) {
    __shared__ __align__(16) char sraw[49152];
    float4* W1sh = (float4*)sraw;             // 32KB
    char*   W2b  = sraw + 32768;              // 16KB
    float*  red  = (float*)sraw;              // overlay after main loop (32KB)

    int h   = blockIdx.x;
    int tid = threadIdx.x;
    int w   = tid >> 5;
    int t   = tid & 31;

    // ---------- Param computation (lanes 2q, 2q+1 both compute n = 16w+q) ----------
    int nloc = t >> 1;
    int hh   = t & 1;
    int n_me = w * NPW + nloc;
    int gi   = h * NST + n_me;

    float wr, wi, w32r, w32i, w64r, w64i, cmr, cmi, cm1024r, cm1024i;
    {
        float dt  = __expf(inv_dt[h]);
        float Are = -__expf(A_real[gi]);
        float Aim = A_imag[gi];
        float ar  = Are * dt;     // < 0
        float ai  = Aim * dt;

        float ea = __expf(ar);
        float sa, ca; my_sincos(ai, &sa, &ca);
        wr = ea * ca;
        wi = ea * sa;
        float er = wr - 1.0f;
        float ei = wi;

        float inv = 1.0f / fmaf(Are, Are, Aim * Aim);
        float fr = (er * Are + ei * Aim) * inv;
        float fi = (ei * Are - er * Aim) * inv;

        float br  = Bg[2 * gi], bi  = Bg[2 * gi + 1];
        float c0r = Cg[2 * gi], c0i = Cg[2 * gi + 1];
        float bcr = br * c0r - bi * c0i;
        float bci = br * c0i + bi * c0r;
        cmr = 2.0f * (bcr * fr - bci * fi);
        cmi = 2.0f * (bcr * fi + bci * fr);

        float e32 = __expf(32.0f * ar);
        float s32, c32; my_sincos(32.0f * ai, &s32, &c32);
        w32r = e32 * c32;
        w32i = e32 * s32;

        w64r = fmaf(w32r, w32r, -(w32i * w32i));
        w64i = 2.0f * w32r * w32i;
        float xr = w64r, xi = w64i;
#pragma unroll
        for (int s = 0; s < 4; s++) {              // w^1024 = (w^64)^16
            float nr = fmaf(xr, xr, -(xi * xi));
            float ni = 2.0f * xr * xi;
            xr = nr; xi = ni;
        }
        cm1024r = fmaf(cmr, xr, -(cmi * xi));
        cm1024i = fmaf(cmr, xi,  cmi * xr);
    }

    // ---------- Table generation: thread (n_me, hh) ----------
    {
        int swz = n_me & 31;

        // W1 chain: hh=0 -> w^0..w^31 into .xy, hh=1 -> w^32..w^63 into .zw
        float cr = hh ? w32r : 1.0f;
        float ci = hh ? w32i : 0.0f;
        char* w1base = (char*)(W1sh + n_me * 32) + hh * 8;
#pragma unroll
        for (int k = 0; k < 32; k++) {
            *(float2*)(w1base + (k ^ swz) * 16) = make_float2(cr, ci);
            float nr = fmaf(cr, wr, -(ci * wi));
            float ni = fmaf(cr, wi,   ci * wr);
            cr = nr; ci = ni;
        }

        // W2 chain: hh=0 -> j2=0..15 (seed Cm), hh=1 -> j2=16..31 (seed Cm*w^1024)
        // Store at [p][n]: byte offset (p*64 + n)*16 + (j2&1)*8, p = j2>>1.
        float sr = hh ? cm1024r : cmr;
        float si = hh ? cm1024i : cmi;
#pragma unroll
        for (int k = 0; k < 16; k++) {
            int j2 = hh * 16 + k;
            int p  = j2 >> 1;
            *(float2*)(W2b + (p * 64 + n_me) * 16 + (j2 & 1) * 8) = make_float2(sr, si);
            float nr = fmaf(sr, w64r, -(si * w64i));
            float ni = fmaf(sr, w64i,   si * w64r);
            sr = nr; si = ni;
        }
    }
    __syncthreads();

    // ---------- Main contraction ----------
    float accA[32], accB[32];
#pragma unroll
    for (int j = 0; j < 32; j++) { accA[j] = 0.0f; accB[j] = 0.0f; }

    const int nbase = w * NPW;
#pragma unroll
    for (int nn = 0; nn < NPW; nn++) {
        int n = nbase + nn;
        float4 w1 = W1sh[n * 32 + (t ^ (n & 31))];          // (w^t, w^(t+32))
        const char* w2n = W2b + n * 16;                     // p-offsets immediate
#pragma unroll
        for (int p = 0; p < 16; p++) {
            float4 w2 = *(const float4*)(w2n + p * 1024);   // broadcast
            int j0 = 2 * p, j1 = 2 * p + 1;
            accA[j0] = fmaf(w2.x, w1.x, accA[j0]);
            accA[j0] = fmaf(-w2.y, w1.y, accA[j0]);
            accA[j1] = fmaf(w2.z, w1.x, accA[j1]);
            accA[j1] = fmaf(-w2.w, w1.y, accA[j1]);
            accB[j0] = fmaf(w2.x, w1.z, accB[j0]);
            accB[j0] = fmaf(-w2.y, w1.w, accB[j0]);
            accB[j1] = fmaf(w2.z, w1.z, accB[j1]);
            accB[j1] = fmaf(-w2.w, w1.w, accB[j1]);
        }
    }
    __syncthreads();   // all W1/W2 reads done before overlay

    // ---------- Stage partials: red[w][a][t], a = half*32 + j2 ----------
#pragma unroll
    for (int j = 0; j < 32; j++) {
        red[(w * 64 + j) * 32 + t]      = accA[j];
        red[(w * 64 + 32 + j) * 32 + t] = accB[j];
    }
    __syncthreads();

    // ---------- Reduce 4 warps, store coalesced ----------
    float* o = out + h * LL;
    for (int e = tid; e < LL; e += 32 * NWARP) {
        int j2 = e >> 6;
        int j1 = e & 63;
        int a  = ((j1 >> 5) << 5) + j2;
        int tt = j1 & 31;
        float s = red[(0 * 64 + a) * 32 + tt] + red[(1 * 64 + a) * 32 + tt]
                + red[(2 * 64 + a) * 32 + tt] + red[(3 * 64 + a) * 32 + tt];
        o[e] = s;
    }
}

extern "C" void kernel_launch(void* const* d_in, const int* in_sizes, int n_in,
                              void* d_out, int out_size) {
    const float* A_real = (const float*)d_in[0];
    const float* A_imag = (const float*)d_in[1];
    const float* B      = (const float*)d_in[2];
    const float* C      = (const float*)d_in[3];
    const float* inv_dt = (const float*)d_in[4];
    float* out = (float*)d_out;

    s4d_all<<<HH, 32 * NWARP>>>(A_real, A_imag, B, C, inv_dt, out);
}

// round 9
// speedup vs baseline: 1.1271x; 1.1271x over previous
#include <cuda_runtime.h>

#define HH    1024
#define NST   64
#define LL    2048
#define NWARP 4

// Accurate sincos for |x| <= ~110, independent of compiler fast-math flags.
__device__ __forceinline__ void my_sincos(float x, float* sp, float* cp) {
    float k = rintf(x * 0.63661977236f);           // x * 2/pi
    float r = fmaf(k, -1.57079637e+0f, x);         // x - k*PIO2_HI
    r = fmaf(k, 4.37113900e-8f, r);                // + k*PIO2_MID
    int q = ((int)k) & 3;
    float r2 = r * r;
    float s0 = fmaf(r2, -1.9515296e-4f, 8.3321609e-3f);
    s0 = fmaf(r2, s0, -1.6666655e-1f);
    float sr = fmaf(r * r2, s0, r);
    float c0 = fmaf(r2, 2.4433157e-5f, -1.3887316e-3f);
    c0 = fmaf(r2, c0, 4.1666646e-2f);
    c0 = fmaf(r2, c0, -0.5f);
    float cr = fmaf(r2, c0, 1.0f);
    float ss = (q & 1) ? cr : sr;
    float cc = (q & 1) ? sr : cr;
    if (q == 1 || q == 2) cc = -cc;
    if (q >= 2) ss = -ss;
    *sp = ss; *cp = cc;
}

// Single fused kernel. One CTA per h, 4 warps.
// Chirp factorization: l = j1 + 64*j2 (j1<64, j2<32):
//   K[h,l] = sum_n Re( W2[n,j2] * W1[n,j1] ),
//   W1[n,j1] = w_n^j1,  W2[n,j2] = Cm_n * (w_n^64)^j2   (2x folded into Cm).
// W1sh: [64 n][32 slots] float4 = (w^t, w^(t+32)), slot = t XOR (n&31). 32KB.
// W2sh: [16 p][64 n] float4 = (W2[n][2p], W2[n][2p+1]); broadcast reads at
//       base + n*16B + p*1024B (p-offsets are LDS immediates). 16KB.
// WORK SPLIT: warp w owns j2 in [8w, 8w+8) for ALL 64 n. Every output
// element is completed inside one warp -> no cross-warp reduction, no staging,
// direct coalesced stores. Lane t holds j1 = t (accA) and j1 = t+32 (accB).
__global__ void __launch_bounds__(32 * NWARP, 4) s4d_all(
        const float* __restrict__ A_real,
        const float* __restrict__ A_imag,
        const float* __restrict__ Bg,
        const float* __restrict__ Cg,
        const float* __restrict__ inv_dt,
        float* __restrict__ out) {
    __shared__ __align__(16) char sraw[49152];
    float4* W1sh = (float4*)sraw;             // 32KB
    char*   W2b  = sraw + 32768;              // 16KB

    int h   = blockIdx.x;
    int tid = threadIdx.x;
    int w   = tid >> 5;
    int t   = tid & 31;

    // ---------- Param computation (lanes 2q, 2q+1 both compute n = 16w+q) ----------
    int nloc = t >> 1;
    int hh   = t & 1;
    int n_me = w * 16 + nloc;
    int gi   = h * NST + n_me;

    float wr, wi, w32r, w32i, w64r, w64i, cmr, cmi, cm1024r, cm1024i;
    {
        float dt  = __expf(inv_dt[h]);
        float Are = -__expf(A_real[gi]);
        float Aim = A_imag[gi];
        float ar  = Are * dt;     // < 0
        float ai  = Aim * dt;

        float ea = __expf(ar);
        float sa, ca; my_sincos(ai, &sa, &ca);
        wr = ea * ca;
        wi = ea * sa;
        float er = wr - 1.0f;
        float ei = wi;

        float inv = 1.0f / fmaf(Are, Are, Aim * Aim);
        float fr = (er * Are + ei * Aim) * inv;
        float fi = (ei * Are - er * Aim) * inv;

        float br  = Bg[2 * gi], bi  = Bg[2 * gi + 1];
        float c0r = Cg[2 * gi], c0i = Cg[2 * gi + 1];
        float bcr = br * c0r - bi * c0i;
        float bci = br * c0i + bi * c0r;
        cmr = 2.0f * (bcr * fr - bci * fi);
        cmi = 2.0f * (bcr * fi + bci * fr);

        float e32 = __expf(32.0f * ar);
        float s32, c32; my_sincos(32.0f * ai, &s32, &c32);
        w32r = e32 * c32;
        w32i = e32 * s32;

        w64r = fmaf(w32r, w32r, -(w32i * w32i));
        w64i = 2.0f * w32r * w32i;
        float xr = w64r, xi = w64i;
#pragma unroll
        for (int s = 0; s < 4; s++) {              // w^1024 = (w^64)^16
            float nr = fmaf(xr, xr, -(xi * xi));
            float ni = 2.0f * xr * xi;
            xr = nr; xi = ni;
        }
        cm1024r = fmaf(cmr, xr, -(cmi * xi));
        cm1024i = fmaf(cmr, xi,  cmi * xr);
    }

    // ---------- Table generation: thread (n_me, hh) ----------
    {
        int swz = n_me & 31;

        // W1 chain: hh=0 -> w^0..w^31 into .xy, hh=1 -> w^32..w^63 into .zw
        float cr = hh ? w32r : 1.0f;
        float ci = hh ? w32i : 0.0f;
        char* w1base = (char*)(W1sh + n_me * 32) + hh * 8;
#pragma unroll
        for (int k = 0; k < 32; k++) {
            *(float2*)(w1base + (k ^ swz) * 16) = make_float2(cr, ci);
            float nr = fmaf(cr, wr, -(ci * wi));
            float ni = fmaf(cr, wi,   ci * wr);
            cr = nr; ci = ni;
        }

        // W2 chain: hh=0 -> j2=0..15 (seed Cm), hh=1 -> j2=16..31 (seed Cm*w^1024)
        // Store at [p][n]: byte offset (p*64 + n)*16 + (j2&1)*8, p = j2>>1.
        float sr = hh ? cm1024r : cmr;
        float si = hh ? cm1024i : cmi;
#pragma unroll
        for (int k = 0; k < 16; k++) {
            int j2 = hh * 16 + k;
            int p  = j2 >> 1;
            *(float2*)(W2b + (p * 64 + n_me) * 16 + (j2 & 1) * 8) = make_float2(sr, si);
            float nr = fmaf(sr, w64r, -(si * w64i));
            float ni = fmaf(sr, w64i,   si * w64r);
            sr = nr; si = ni;
        }
    }
    __syncthreads();

    // ---------- Main contraction: warp w covers j2 in [8w, 8w+8), all n ----------
    float accA[8], accB[8];
#pragma unroll
    for (int j = 0; j < 8; j++) { accA[j] = 0.0f; accB[j] = 0.0f; }

    // This warp's 4 W2 pair-rows: p = 4w + pp, byte offset (p*64 + n)*16.
    const char* w2base = W2b + (w * 4) * 1024;

#pragma unroll 16
    for (int n = 0; n < NST; n++) {
        float4 w1 = W1sh[n * 32 + (t ^ (n & 31))];            // (w^t, w^(t+32))
        const char* w2n = w2base + n * 16;                    // pp-offsets immediate
#pragma unroll
        for (int pp = 0; pp < 4; pp++) {
            float4 w2 = *(const float4*)(w2n + pp * 1024);    // broadcast
            int j0 = 2 * pp, j1 = 2 * pp + 1;
            accA[j0] = fmaf(w2.x, w1.x, accA[j0]);
            accA[j0] = fmaf(-w2.y, w1.y, accA[j0]);
            accA[j1] = fmaf(w2.z, w1.x, accA[j1]);
            accA[j1] = fmaf(-w2.w, w1.y, accA[j1]);
            accB[j0] = fmaf(w2.x, w1.z, accB[j0]);
            accB[j0] = fmaf(-w2.y, w1.w, accB[j0]);
            accB[j1] = fmaf(w2.z, w1.z, accB[j1]);
            accB[j1] = fmaf(-w2.w, w1.w, accB[j1]);
        }
    }

    // ---------- Direct coalesced stores: l = j1 + 64*j2 ----------
    float* o = out + h * LL + (w * 8) * 64 + t;   // j2 = 8w + j
#pragma unroll
    for (int j = 0; j < 8; j++) {
        o[j * 64]      = accA[j];   // j1 = t
        o[j * 64 + 32] = accB[j];   // j1 = t + 32
    }
}

extern "C" void kernel_launch(void* const* d_in, const int* in_sizes, int n_in,
                              void* d_out, int out_size) {
    const float* A_real = (const float*)d_in[0];
    const float* A_imag = (const float*)d_in[1];
    const float* B      = (const float*)d_in[2];
    const float* C      = (const float*)d_in[3];
    const float* inv_dt = (const float*)d_in[4];
    float* out = (float*)d_out;

    s4d_all<<<HH, 32 * NWARP>>>(A_real, A_imag, B, C, inv_dt, out);
}

// round 12
// speedup vs baseline: 1.3589x; 1.2056x over previous
#include <cuda_runtime.h>
#include <cstdint>

#define HH    1024
#define NST   64
#define LL    2048
#define NWARP 4

// Accurate sincos for |x| <= ~110, independent of compiler fast-math flags.
__device__ __forceinline__ void my_sincos(float x, float* sp, float* cp) {
    float k = rintf(x * 0.63661977236f);           // x * 2/pi
    float r = fmaf(k, -1.57079637e+0f, x);         // x - k*PIO2_HI
    r = fmaf(k, 4.37113900e-8f, r);                // + k*PIO2_MID
    int q = ((int)k) & 3;
    float r2 = r * r;
    float s0 = fmaf(r2, -1.9515296e-4f, 8.3321609e-3f);
    s0 = fmaf(r2, s0, -1.6666655e-1f);
    float sr = fmaf(r * r2, s0, r);
    float c0 = fmaf(r2, 2.4433157e-5f, -1.3887316e-3f);
    c0 = fmaf(r2, c0, 4.1666646e-2f);
    c0 = fmaf(r2, c0, -0.5f);
    float cr = fmaf(r2, c0, 1.0f);
    float ss = (q & 1) ? cr : sr;
    float cc = (q & 1) ? sr : cr;
    if (q == 1 || q == 2) cc = -cc;
    if (q >= 2) ss = -ss;
    *sp = ss; *cp = cc;
}

// One CTA per h, 4 warps. Tensor-core formulation:
//   K[j1, j2] = sum_k A[j1, k] * B[k, j2], k-tiles kt of 8: within a kt,
//   col c (0-3)  = W1r[n = 4kt + c][j1],
//   col c+4      = W1i[n = 4kt + c][j1],
//   B row 8kt+c   = W2r[n],  B row 8kt+c+4 = -W2i[n]
// so sum = Re(W2 * W1) with W1 = w^j1, W2 = Cm*(w^64)^j2 (2x folded). l = j1 + 64*j2.
//
// m16n8k8 tf32 fragment layout (PTX): groupID r = t>>2, tig c = t&3.
//   A: a0=(r, c) a1=(r+8, c) a2=(r, c+4) a3=(r+8, c+4)
//   B: b0=(row c, col r) b1=(row c+4, col r)
//   C: c0=(r, 2c) c1=(r, 2c+1) c2=(r+8, 2c) c3=(r+8, 2c+1)
// With the re/im col split, one LDS.64 of (W1r, W1i)[n=4kt+c] yields (a0, a2).
//
// B is split into tf32 hi+lo at preload (held in 64 regs); 2 mma per (kt, mt)
// kill B's tf32 rounding error -> residual error is A's tf32 rounding only.
//
// Warp w owns j2 in [8w, 8w+8).
// As: [16 kt][64 j1][4 pair-slots] float2 = 32KB.
// Bs: [128 krow][32 j2 XOR (krow&31)] fp32 = 16KB.
__global__ void __launch_bounds__(32 * NWARP, 4) s4d_all(
        const float* __restrict__ A_real,
        const float* __restrict__ A_imag,
        const float* __restrict__ Bg,
        const float* __restrict__ Cg,
        const float* __restrict__ inv_dt,
        float* __restrict__ out) {
    __shared__ __align__(16) float As[16 * 512];   // 32KB
    __shared__ __align__(16) float Bs[128 * 32];   // 16KB

    int h   = blockIdx.x;
    int tid = threadIdx.x;
    int w   = tid >> 5;
    int t   = tid & 31;

    // ---------- Param computation (lanes 2q, 2q+1 both compute n = 16w+q) ----------
    int q_   = t >> 1;
    int hh   = t & 1;
    int n_me = w * 16 + q_;
    int gi   = h * NST + n_me;

    float wr, wi, w32r, w32i, w64r, w64i, cmr, cmi, cm1024r, cm1024i;
    {
        float dt  = __expf(inv_dt[h]);
        float Are = -__expf(A_real[gi]);
        float Aim = A_imag[gi];
        float ar  = Are * dt;     // < 0
        float ai  = Aim * dt;

        float ea = __expf(ar);
        float sa, ca; my_sincos(ai, &sa, &ca);
        wr = ea * ca;
        wi = ea * sa;
        float er = wr - 1.0f;
        float ei = wi;

        float inv = 1.0f / fmaf(Are, Are, Aim * Aim);
        float fr = (er * Are + ei * Aim) * inv;
        float fi = (ei * Are - er * Aim) * inv;

        float br  = Bg[2 * gi], bi  = Bg[2 * gi + 1];
        float c0r = Cg[2 * gi], c0i = Cg[2 * gi + 1];
        float bcr = br * c0r - bi * c0i;
        float bci = br * c0i + bi * c0r;
        cmr = 2.0f * (bcr * fr - bci * fi);
        cmi = 2.0f * (bcr * fi + bci * fr);

        float e32 = __expf(32.0f * ar);
        float s32, c32; my_sincos(32.0f * ai, &s32, &c32);
        w32r = e32 * c32;
        w32i = e32 * s32;

        w64r = fmaf(w32r, w32r, -(w32i * w32i));
        w64i = 2.0f * w32r * w32i;
        float xr = w64r, xi = w64i;
#pragma unroll
        for (int s = 0; s < 4; s++) {              // w^1024 = (w^64)^16
            float nr = fmaf(xr, xr, -(xi * xi));
            float ni = 2.0f * xr * xi;
            xr = nr; xi = ni;
        }
        cm1024r = fmaf(cmr, xr, -(cmi * xi));
        cm1024i = fmaf(cmr, xi,  cmi * xr);
    }

    // ---------- W1 chain -> A table ----------
    // Thread (n_me, hh) covers j1 in [32hh, 32hh+32), chain start rotated by
    // rot = (n>>2)&3 so simultaneous writers hit distinct banks.
    {
        int rot = (n_me >> 2) & 3;
        float w2r_ = fmaf(wr, wr, -(wi * wi));
        float w2i_ = 2.0f * wr * wi;
        float w3r_ = fmaf(w2r_, wr, -(w2i_ * wi));
        float w3i_ = fmaf(w2r_, wi,   w2i_ * wr);
        float wror = (rot == 0) ? 1.0f : (rot == 1) ? wr : (rot == 2) ? w2r_ : w3r_;
        float wroi = (rot == 0) ? 0.0f : (rot == 1) ? wi : (rot == 2) ? w2i_ : w3i_;
        float sAr = hh ? w32r : 1.0f;
        float sAi = hh ? w32i : 0.0f;
        float cr = fmaf(sAr, wror, -(sAi * wroi));   // w^(32hh + rot)
        float ci = fmaf(sAr, wroi,   sAi * wror);

        // float2 slot: kt0*256 + j1*4 + (n&3),  kt0 = n>>2
        float2* abase = (float2*)As + (n_me >> 2) * 256 + (n_me & 3);
        int jbase = 32 * hh;
        int j = rot;
#pragma unroll
        for (int s = 0; s < 32; s++) {
            abase[(jbase + j) * 4] = make_float2(cr, ci);
            float nr = fmaf(cr, wr, -(ci * wi));
            float ni = fmaf(cr, wi,   ci * wr);
            cr = nr; ci = ni;
            j++;
            if (j == 32) { j = 0; cr = sAr; ci = sAi; }   // wrap: reseed to w^(32hh)
        }
    }

    // ---------- W2 chain -> B table ----------
    // Thread (n_me, hh): j2 in [16hh, 16hh+16).
    // Rows: re at 8*(n>>2) + (n&3), im (negated) at +4. Column XOR (row&31).
    {
        float sr = hh ? cm1024r : cmr;
        float si = hh ? cm1024i : cmi;
        int krR = (n_me >> 2) * 8 + (n_me & 3);
        int krI = krR + 4;
        float* bR = Bs + krR * 32;
        float* bI = Bs + krI * 32;
        int xR = krR & 31;
        int xI = krI & 31;
#pragma unroll
        for (int k2 = 0; k2 < 16; k2++) {
            int j2 = hh * 16 + k2;
            bR[j2 ^ xR] = sr;
            bI[j2 ^ xI] = -si;
            float nr = fmaf(sr, w64r, -(si * w64i));
            float ni = fmaf(sr, w64i,   si * w64r);
            sr = nr; si = ni;
        }
    }
    __syncthreads();

    // ---------- Preload B fragments, split hi/lo tf32 (held in regs) ----------
    int c = t & 3;        // threadID_in_group
    int r = t >> 2;       // groupID
    uint32_t ub0h[16], ub0l[16], ub1h[16], ub1l[16];
    {
        int j2col = 8 * w + r;
#pragma unroll
        for (int kt = 0; kt < 16; kt++) {
            int row0 = kt * 8 + c;        // W2r row
            int row1 = row0 + 4;          // -W2i row
            float b0 = Bs[row0 * 32 + (j2col ^ (row0 & 31))];
            float b1 = Bs[row1 * 32 + (j2col ^ (row1 & 31))];
            asm("cvt.rna.tf32.f32 %0, %1;" : "=r"(ub0h[kt]) : "f"(b0));
            asm("cvt.rna.tf32.f32 %0, %1;" : "=r"(ub1h[kt]) : "f"(b1));
            float b0l = b0 - __uint_as_float(ub0h[kt]);
            float b1l = b1 - __uint_as_float(ub1h[kt]);
            asm("cvt.rna.tf32.f32 %0, %1;" : "=r"(ub0l[kt]) : "f"(b0l));
            asm("cvt.rna.tf32.f32 %0, %1;" : "=r"(ub1l[kt]) : "f"(b1l));
        }
    }

    // ---------- Main loop: 16 kt x 4 mt, 2 mma each (B hi + B lo) ----------
    float d0[4], d1[4], d2[4], d3[4];
#pragma unroll
    for (int mt = 0; mt < 4; mt++) { d0[mt] = 0.f; d1[mt] = 0.f; d2[mt] = 0.f; d3[mt] = 0.f; }

    const float2* Ap = (const float2*)As;
#pragma unroll
    for (int kt = 0; kt < 16; kt++) {
#pragma unroll
        for (int mt = 0; mt < 4; mt++) {
            // (W1r, W1i) of n = 4kt + c at rows r and r+8 of this m-tile.
            float2 a01 = Ap[kt * 256 + (mt * 16 + r) * 4 + c];
            float2 a23 = Ap[kt * 256 + (mt * 16 + 8 + r) * 4 + c];
            uint32_t ua0, ua1, ua2, ua3;
            asm("cvt.rna.tf32.f32 %0, %1;" : "=r"(ua0) : "f"(a01.x));  // (r,   c)
            asm("cvt.rna.tf32.f32 %0, %1;" : "=r"(ua1) : "f"(a23.x));  // (r+8, c)
            asm("cvt.rna.tf32.f32 %0, %1;" : "=r"(ua2) : "f"(a01.y));  // (r,   c+4)
            asm("cvt.rna.tf32.f32 %0, %1;" : "=r"(ua3) : "f"(a23.y));  // (r+8, c+4)
            asm("mma.sync.aligned.m16n8k8.row.col.f32.tf32.tf32.f32 "
                "{%0,%1,%2,%3}, {%4,%5,%6,%7}, {%8,%9}, {%0,%1,%2,%3};"
                : "+f"(d0[mt]), "+f"(d1[mt]), "+f"(d2[mt]), "+f"(d3[mt])
                : "r"(ua0), "r"(ua1), "r"(ua2), "r"(ua3),
                  "r"(ub0h[kt]), "r"(ub1h[kt]));
            asm("mma.sync.aligned.m16n8k8.row.col.f32.tf32.tf32.f32 "
                "{%0,%1,%2,%3}, {%4,%5,%6,%7}, {%8,%9}, {%0,%1,%2,%3};"
                : "+f"(d0[mt]), "+f"(d1[mt]), "+f"(d2[mt]), "+f"(d3[mt])
                : "r"(ua0), "r"(ua1), "r"(ua2), "r"(ua3),
                  "r"(ub0l[kt]), "r"(ub1l[kt]));
        }
    }

    // ---------- Epilogue: C frag -> out[h, j1 + 64*j2] ----------
    float* o = out + h * LL;
    int j2a = 8 * w + 2 * c;
#pragma unroll
    for (int mt = 0; mt < 4; mt++) {
        int row = mt * 16 + r;
        o[row     + 64 * j2a]       = d0[mt];
        o[row     + 64 * (j2a + 1)] = d1[mt];
        o[row + 8 + 64 * j2a]       = d2[mt];
        o[row + 8 + 64 * (j2a + 1)] = d3[mt];
    }
}

extern "C" void kernel_launch(void* const* d_in, const int* in_sizes, int n_in,
                              void* d_out, int out_size) {
    const float* A_real = (const float*)d_in[0];
    const float* A_imag = (const float*)d_in[1];
    const float* B      = (const float*)d_in[2];
    const float* C      = (const float*)d_in[3];
    const float* inv_dt = (const float*)d_in[4];
    float* out = (float*)d_out;

    s4d_all<<<HH, 32 * NWARP>>>(A_real, A_imag, B, C, inv_dt, out);
}

// round 15
// speedup vs baseline: 1.3614x; 1.0019x over previous
#include <cuda_runtime.h>
#include <cstdint>

#define HH    1024
#define NST   64
#define LL    2048
#define NWARP 4

// Accurate sincos for |x| <= ~110, independent of compiler fast-math flags.
__device__ __forceinline__ void my_sincos(float x, float* sp, float* cp) {
    float k = rintf(x * 0.63661977236f);           // x * 2/pi
    float r = fmaf(k, -1.57079637e+0f, x);         // x - k*PIO2_HI
    r = fmaf(k, 4.37113900e-8f, r);                // + k*PIO2_MID
    int q = ((int)k) & 3;
    float r2 = r * r;
    float s0 = fmaf(r2, -1.9515296e-4f, 8.3321609e-3f);
    s0 = fmaf(r2, s0, -1.6666655e-1f);
    float sr = fmaf(r * r2, s0, r);
    float c0 = fmaf(r2, 2.4433157e-5f, -1.3887316e-3f);
    c0 = fmaf(r2, c0, 4.1666646e-2f);
    c0 = fmaf(r2, c0, -0.5f);
    float cr = fmaf(r2, c0, 1.0f);
    float ss = (q & 1) ? cr : sr;
    float cc = (q & 1) ? sr : cr;
    if (q == 1 || q == 2) cc = -cc;
    if (q >= 2) ss = -ss;
    *sp = ss; *cp = cc;
}

__device__ __forceinline__ float tf32r(float x) {
    uint32_t u;
    asm("cvt.rna.tf32.f32 %0, %1;" : "=r"(u) : "f"(x));
    return __uint_as_float(u);
}

// One CTA per h, 4 warps. Tensor-core formulation:
//   K[j1, j2] = sum_k A[j1, k] * B[k, j2], k-tiles kt of 8: within a kt,
//   col c (0-3)  = W1r[n = 4kt + c][j1],
//   col c+4      = W1i[n = 4kt + c][j1],
//   B row 8kt+c   = W2r[n],  B row 8kt+c+4 = -W2i[n]
// so sum = Re(W2 * W1) with W1 = w^j1, W2 = Cm*(w^64)^j2 (2x folded). l = j1 + 64*j2.
//
// m16n8k8 tf32 fragment layout (PTX): groupID r = t>>2, tig c = t&3.
//   A: a0=(r, c) a1=(r+8, c) a2=(r, c+4) a3=(r+8, c+4)
//   B: b0=(row c, col r) b1=(row c+4, col r)
//   C: c0=(r, 2c) c1=(r, 2c+1) c2=(r+8, 2c) c3=(r+8, 2c+1)
// One LDS.64 of (W1r, W1i)[n=4kt+c] yields (a0, a2).
//
// A values are tf32-rounded AT TABLE GENERATION (rounding is idempotent; chain
// state stays fp32) -> the main loop feeds loaded bits directly to mma: zero
// per-iteration cvt. B is split into tf32 hi+lo at preload (64 regs); 2 mma
// per (kt, mt) kill B's rounding error.
//
// Warp w owns j2 in [8w, 8w+8).
// As: [16 kt][64 j1][4 pair-slots] float2 = 32KB (tf32-rounded values).
// Bs: [128 krow][32 j2 XOR (krow&31)] fp32 = 16KB.
__global__ void __launch_bounds__(32 * NWARP, 4) s4d_all(
        const float* __restrict__ A_real,
        const float* __restrict__ A_imag,
        const float* __restrict__ Bg,
        const float* __restrict__ Cg,
        const float* __restrict__ inv_dt,
        float* __restrict__ out) {
    __shared__ __align__(16) float As[16 * 512];   // 32KB
    __shared__ __align__(16) float Bs[128 * 32];   // 16KB

    int h   = blockIdx.x;
    int tid = threadIdx.x;
    int w   = tid >> 5;
    int t   = tid & 31;

    // ---------- Param computation (lanes 2q, 2q+1 both compute n = 16w+q) ----------
    int q_   = t >> 1;
    int hh   = t & 1;
    int n_me = w * 16 + q_;
    int gi   = h * NST + n_me;

    float wr, wi, w32r, w32i, w64r, w64i, cmr, cmi, cm1024r, cm1024i;
    {
        float dt  = __expf(inv_dt[h]);
        float Are = -__expf(A_real[gi]);
        float Aim = A_imag[gi];
        float ar  = Are * dt;     // < 0
        float ai  = Aim * dt;

        float ea = __expf(ar);
        float sa, ca; my_sincos(ai, &sa, &ca);
        wr = ea * ca;
        wi = ea * sa;
        float er = wr - 1.0f;
        float ei = wi;

        float inv = 1.0f / fmaf(Are, Are, Aim * Aim);
        float fr = (er * Are + ei * Aim) * inv;
        float fi = (ei * Are - er * Aim) * inv;

        float br  = Bg[2 * gi], bi  = Bg[2 * gi + 1];
        float c0r = Cg[2 * gi], c0i = Cg[2 * gi + 1];
        float bcr = br * c0r - bi * c0i;
        float bci = br * c0i + bi * c0r;
        cmr = 2.0f * (bcr * fr - bci * fi);
        cmi = 2.0f * (bcr * fi + bci * fr);

        float e32 = __expf(32.0f * ar);
        float s32, c32; my_sincos(32.0f * ai, &s32, &c32);
        w32r = e32 * c32;
        w32i = e32 * s32;

        w64r = fmaf(w32r, w32r, -(w32i * w32i));
        w64i = 2.0f * w32r * w32i;
        float xr = w64r, xi = w64i;
#pragma unroll
        for (int s = 0; s < 4; s++) {              // w^1024 = (w^64)^16
            float nr = fmaf(xr, xr, -(xi * xi));
            float ni = 2.0f * xr * xi;
            xr = nr; xi = ni;
        }
        cm1024r = fmaf(cmr, xr, -(cmi * xi));
        cm1024i = fmaf(cmr, xi,  cmi * xr);
    }

    // ---------- W1 chain -> A table (stored tf32-rounded) ----------
    // Thread (n_me, hh) covers j1 in [32hh, 32hh+32), chain start rotated by
    // rot = (n>>2)&3 so simultaneous writers hit distinct banks.
    {
        int rot = (n_me >> 2) & 3;
        float w2r_ = fmaf(wr, wr, -(wi * wi));
        float w2i_ = 2.0f * wr * wi;
        float w3r_ = fmaf(w2r_, wr, -(w2i_ * wi));
        float w3i_ = fmaf(w2r_, wi,   w2i_ * wr);
        float wror = (rot == 0) ? 1.0f : (rot == 1) ? wr : (rot == 2) ? w2r_ : w3r_;
        float wroi = (rot == 0) ? 0.0f : (rot == 1) ? wi : (rot == 2) ? w2i_ : w3i_;
        float sAr = hh ? w32r : 1.0f;
        float sAi = hh ? w32i : 0.0f;
        float cr = fmaf(sAr, wror, -(sAi * wroi));   // w^(32hh + rot)
        float ci = fmaf(sAr, wroi,   sAi * wror);

        // float2 slot: kt0*256 + j1*4 + (n&3),  kt0 = n>>2
        float2* abase = (float2*)As + (n_me >> 2) * 256 + (n_me & 3);
        int jbase = 32 * hh;
        int j = rot;
#pragma unroll
        for (int s = 0; s < 32; s++) {
            abase[(jbase + j) * 4] = make_float2(tf32r(cr), tf32r(ci));
            float nr = fmaf(cr, wr, -(ci * wi));
            float ni = fmaf(cr, wi,   ci * wr);
            cr = nr; ci = ni;
            j++;
            if (j == 32) { j = 0; cr = sAr; ci = sAi; }   // wrap: reseed to w^(32hh)
        }
    }

    // ---------- W2 chain -> B table ----------
    // Thread (n_me, hh): j2 in [16hh, 16hh+16).
    // Rows: re at 8*(n>>2) + (n&3), im (negated) at +4. Column XOR (row&31).
    {
        float sr = hh ? cm1024r : cmr;
        float si = hh ? cm1024i : cmi;
        int krR = (n_me >> 2) * 8 + (n_me & 3);
        int krI = krR + 4;
        float* bR = Bs + krR * 32;
        float* bI = Bs + krI * 32;
        int xR = krR & 31;
        int xI = krI & 31;
#pragma unroll
        for (int k2 = 0; k2 < 16; k2++) {
            int j2 = hh * 16 + k2;
            bR[j2 ^ xR] = sr;
            bI[j2 ^ xI] = -si;
            float nr = fmaf(sr, w64r, -(si * w64i));
            float ni = fmaf(sr, w64i,   si * w64r);
            sr = nr; si = ni;
        }
    }
    __syncthreads();

    // ---------- Preload B fragments, split hi/lo tf32 (held in regs) ----------
    int c = t & 3;        // threadID_in_group
    int r = t >> 2;       // groupID
    uint32_t ub0h[16], ub0l[16], ub1h[16], ub1l[16];
    {
        int j2col = 8 * w + r;
#pragma unroll
        for (int kt = 0; kt < 16; kt++) {
            int row0 = kt * 8 + c;        // W2r row
            int row1 = row0 + 4;          // -W2i row
            float b0 = Bs[row0 * 32 + (j2col ^ (row0 & 31))];
            float b1 = Bs[row1 * 32 + (j2col ^ (row1 & 31))];
            asm("cvt.rna.tf32.f32 %0, %1;" : "=r"(ub0h[kt]) : "f"(b0));
            asm("cvt.rna.tf32.f32 %0, %1;" : "=r"(ub1h[kt]) : "f"(b1));
            float b0l = b0 - __uint_as_float(ub0h[kt]);
            float b1l = b1 - __uint_as_float(ub1h[kt]);
            asm("cvt.rna.tf32.f32 %0, %1;" : "=r"(ub0l[kt]) : "f"(b0l));
            asm("cvt.rna.tf32.f32 %0, %1;" : "=r"(ub1l[kt]) : "f"(b1l));
        }
    }

    // ---------- Main loop: 16 kt x 4 mt, 2 mma each (B hi + B lo), zero cvt ----------
    float d0[4], d1[4], d2[4], d3[4];
#pragma unroll
    for (int mt = 0; mt < 4; mt++) { d0[mt] = 0.f; d1[mt] = 0.f; d2[mt] = 0.f; d3[mt] = 0.f; }

    const float2* Ap = (const float2*)As;
#pragma unroll
    for (int kt = 0; kt < 16; kt++) {
#pragma unroll
        for (int mt = 0; mt < 4; mt++) {
            // (W1r, W1i) of n = 4kt + c at rows r and r+8 (already tf32-rounded).
            float2 a01 = Ap[kt * 256 + (mt * 16 + r) * 4 + c];
            float2 a23 = Ap[kt * 256 + (mt * 16 + 8 + r) * 4 + c];
            uint32_t ua0 = __float_as_uint(a01.x);   // (r,   c)
            uint32_t ua1 = __float_as_uint(a23.x);   // (r+8, c)
            uint32_t ua2 = __float_as_uint(a01.y);   // (r,   c+4)
            uint32_t ua3 = __float_as_uint(a23.y);   // (r+8, c+4)
            asm("mma.sync.aligned.m16n8k8.row.col.f32.tf32.tf32.f32 "
                "{%0,%1,%2,%3}, {%4,%5,%6,%7}, {%8,%9}, {%0,%1,%2,%3};"
                : "+f"(d0[mt]), "+f"(d1[mt]), "+f"(d2[mt]), "+f"(d3[mt])
                : "r"(ua0), "r"(ua1), "r"(ua2), "r"(ua3),
                  "r"(ub0h[kt]), "r"(ub1h[kt]));
            asm("mma.sync.aligned.m16n8k8.row.col.f32.tf32.tf32.f32 "
                "{%0,%1,%2,%3}, {%4,%5,%6,%7}, {%8,%9}, {%0,%1,%2,%3};"
                : "+f"(d0[mt]), "+f"(d1[mt]), "+f"(d2[mt]), "+f"(d3[mt])
                : "r"(ua0), "r"(ua1), "r"(ua2), "r"(ua3),
                  "r"(ub0l[kt]), "r"(ub1l[kt]));
        }
    }

    // ---------- Epilogue: C frag -> out[h, j1 + 64*j2] ----------
    float* o = out + h * LL;
    int j2a = 8 * w + 2 * c;
#pragma unroll
    for (int mt = 0; mt < 4; mt++) {
        int row = mt * 16 + r;
        o[row     + 64 * j2a]       = d0[mt];
        o[row     + 64 * (j2a + 1)] = d1[mt];
        o[row + 8 + 64 * j2a]       = d2[mt];
        o[row + 8 + 64 * (j2a + 1)] = d3[mt];
    }
}

extern "C" void kernel_launch(void* const* d_in, const int* in_sizes, int n_in,
                              void* d_out, int out_size) {
    const float* A_real = (const float*)d_in[0];
    const float* A_imag = (const float*)d_in[1];
    const float* B      = (const float*)d_in[2];
    const float* C      = (const float*)d_in[3];
    const float* inv_dt = (const float*)d_in[4];
    float* out = (float*)d_out;

    s4d_all<<<HH, 32 * NWARP>>>(A_real, A_imag, B, C, inv_dt, out);
}

// round 16
// speedup vs baseline: 1.5403x; 1.1314x over previous
#include <cuda_runtime.h>
#include <cstdint>

#define HH    1024
#define NST   64
#define LL    2048
#define NWARP 4

// Accurate sincos for |x| <= ~110, independent of compiler fast-math flags.
__device__ __forceinline__ void my_sincos(float x, float* sp, float* cp) {
    float k = rintf(x * 0.63661977236f);           // x * 2/pi
    float r = fmaf(k, -1.57079637e+0f, x);         // x - k*PIO2_HI
    r = fmaf(k, 4.37113900e-8f, r);                // + k*PIO2_MID
    int q = ((int)k) & 3;
    float r2 = r * r;
    float s0 = fmaf(r2, -1.9515296e-4f, 8.3321609e-3f);
    s0 = fmaf(r2, s0, -1.6666655e-1f);
    float sr = fmaf(r * r2, s0, r);
    float c0 = fmaf(r2, 2.4433157e-5f, -1.3887316e-3f);
    c0 = fmaf(r2, c0, 4.1666646e-2f);
    c0 = fmaf(r2, c0, -0.5f);
    float cr = fmaf(r2, c0, 1.0f);
    float ss = (q & 1) ? cr : sr;
    float cc = (q & 1) ? sr : cr;
    if (q == 1 || q == 2) cc = -cc;
    if (q >= 2) ss = -ss;
    *sp = ss; *cp = cc;
}

__device__ __forceinline__ float tf32r(float x) {
    uint32_t u;
    asm("cvt.rna.tf32.f32 %0, %1;" : "=r"(u) : "f"(x));
    return __uint_as_float(u);
}

// One CTA per h, 4 warps. Tensor-core formulation:
//   K[j1, j2] = sum_k A[j1, k] * B[k, j2], k-tiles kt of 8: within a kt,
//   col c (0-3)  = W1r[n = 4kt + c][j1],
//   col c+4      = W1i[n = 4kt + c][j1],
//   B row 8kt+c   = W2r[n],  B row 8kt+c+4 = -W2i[n]
// so sum = Re(W2 * W1) with W1 = w^j1, W2 = Cm*(w^64)^j2 (2x folded). l = j1 + 64*j2.
//
// m16n8k8 tf32 fragment layout (PTX): groupID r = t>>2, tig c = t&3.
//   A: a0=(r, c) a1=(r+8, c) a2=(r, c+4) a3=(r+8, c+4)
//   B: b0=(row c, col r) b1=(row c+4, col r)
//   C: c0=(r, 2c) c1=(r, 2c+1) c2=(r+8, 2c) c3=(r+8, 2c+1)
// One LDS.64 of (W1r, W1i)[n=4kt+c] yields (a0, a2).
//
// BOTH A and B are tf32-rounded AT TABLE GENERATION (idempotent; chain state
// stays fp32) -> main loop and preload feed loaded bits directly to mma with
// zero cvt; a single mma per (kt, mt). Measured error budget: A-only rounding
// gave 1.92e-4; independent B rounding adds in quadrature -> ~2.8e-4 < 1e-3.
//
// Warp w owns j2 in [8w, 8w+8).
// As: [16 kt][64 j1][4 pair-slots] float2 = 32KB (tf32-rounded).
// Bs: [128 krow][32 j2 XOR (krow&31)] fp32 = 16KB (tf32-rounded).
__global__ void __launch_bounds__(32 * NWARP, 4) s4d_all(
        const float* __restrict__ A_real,
        const float* __restrict__ A_imag,
        const float* __restrict__ Bg,
        const float* __restrict__ Cg,
        const float* __restrict__ inv_dt,
        float* __restrict__ out) {
    __shared__ __align__(16) float As[16 * 512];   // 32KB
    __shared__ __align__(16) float Bs[128 * 32];   // 16KB

    int h   = blockIdx.x;
    int tid = threadIdx.x;
    int w   = tid >> 5;
    int t   = tid & 31;

    // ---------- Param computation (lanes 2q, 2q+1 both compute n = 16w+q) ----------
    int q_   = t >> 1;
    int hh   = t & 1;
    int n_me = w * 16 + q_;
    int gi   = h * NST + n_me;

    float wr, wi, w32r, w32i, w64r, w64i, cmr, cmi, cm1024r, cm1024i;
    {
        float dt  = __expf(inv_dt[h]);
        float Are = -__expf(A_real[gi]);
        float Aim = A_imag[gi];
        float ar  = Are * dt;     // < 0
        float ai  = Aim * dt;

        float ea = __expf(ar);
        float sa, ca; my_sincos(ai, &sa, &ca);
        wr = ea * ca;
        wi = ea * sa;
        float er = wr - 1.0f;
        float ei = wi;

        float inv = 1.0f / fmaf(Are, Are, Aim * Aim);
        float fr = (er * Are + ei * Aim) * inv;
        float fi = (ei * Are - er * Aim) * inv;

        float br  = Bg[2 * gi], bi  = Bg[2 * gi + 1];
        float c0r = Cg[2 * gi], c0i = Cg[2 * gi + 1];
        float bcr = br * c0r - bi * c0i;
        float bci = br * c0i + bi * c0r;
        cmr = 2.0f * (bcr * fr - bci * fi);
        cmi = 2.0f * (bcr * fi + bci * fr);

        float e32 = __expf(32.0f * ar);
        float s32, c32; my_sincos(32.0f * ai, &s32, &c32);
        w32r = e32 * c32;
        w32i = e32 * s32;

        w64r = fmaf(w32r, w32r, -(w32i * w32i));
        w64i = 2.0f * w32r * w32i;
        float xr = w64r, xi = w64i;
#pragma unroll
        for (int s = 0; s < 4; s++) {              // w^1024 = (w^64)^16
            float nr = fmaf(xr, xr, -(xi * xi));
            float ni = 2.0f * xr * xi;
            xr = nr; xi = ni;
        }
        cm1024r = fmaf(cmr, xr, -(cmi * xi));
        cm1024i = fmaf(cmr, xi,  cmi * xr);
    }

    // ---------- W1 chain -> A table (stored tf32-rounded) ----------
    // Thread (n_me, hh) covers j1 in [32hh, 32hh+32), chain start rotated by
    // rot = (n>>2)&3 so simultaneous writers hit distinct banks.
    {
        int rot = (n_me >> 2) & 3;
        float w2r_ = fmaf(wr, wr, -(wi * wi));
        float w2i_ = 2.0f * wr * wi;
        float w3r_ = fmaf(w2r_, wr, -(w2i_ * wi));
        float w3i_ = fmaf(w2r_, wi,   w2i_ * wr);
        float wror = (rot == 0) ? 1.0f : (rot == 1) ? wr : (rot == 2) ? w2r_ : w3r_;
        float wroi = (rot == 0) ? 0.0f : (rot == 1) ? wi : (rot == 2) ? w2i_ : w3i_;
        float sAr = hh ? w32r : 1.0f;
        float sAi = hh ? w32i : 0.0f;
        float cr = fmaf(sAr, wror, -(sAi * wroi));   // w^(32hh + rot)
        float ci = fmaf(sAr, wroi,   sAi * wror);

        // float2 slot: kt0*256 + j1*4 + (n&3),  kt0 = n>>2
        float2* abase = (float2*)As + (n_me >> 2) * 256 + (n_me & 3);
        int jbase = 32 * hh;
        int j = rot;
#pragma unroll
        for (int s = 0; s < 32; s++) {
            abase[(jbase + j) * 4] = make_float2(tf32r(cr), tf32r(ci));
            float nr = fmaf(cr, wr, -(ci * wi));
            float ni = fmaf(cr, wi,   ci * wr);
            cr = nr; ci = ni;
            j++;
            if (j == 32) { j = 0; cr = sAr; ci = sAi; }   // wrap: reseed to w^(32hh)
        }
    }

    // ---------- W2 chain -> B table (stored tf32-rounded) ----------
    // Thread (n_me, hh): j2 in [16hh, 16hh+16).
    // Rows: re at 8*(n>>2) + (n&3), im (negated) at +4. Column XOR (row&31).
    {
        float sr = hh ? cm1024r : cmr;
        float si = hh ? cm1024i : cmi;
        int krR = (n_me >> 2) * 8 + (n_me & 3);
        int krI = krR + 4;
        float* bR = Bs + krR * 32;
        float* bI = Bs + krI * 32;
        int xR = krR & 31;
        int xI = krI & 31;
#pragma unroll
        for (int k2 = 0; k2 < 16; k2++) {
            int j2 = hh * 16 + k2;
            bR[j2 ^ xR] = tf32r(sr);
            bI[j2 ^ xI] = tf32r(-si);
            float nr = fmaf(sr, w64r, -(si * w64i));
            float ni = fmaf(sr, w64i,   si * w64r);
            sr = nr; si = ni;
        }
    }
    __syncthreads();

    // ---------- Preload B fragments (already tf32-rounded; pure LDS + bitcast) ----------
    int c = t & 3;        // threadID_in_group
    int r = t >> 2;       // groupID
    uint32_t ub0[16], ub1[16];
    {
        int j2col = 8 * w + r;
#pragma unroll
        for (int kt = 0; kt < 16; kt++) {
            int row0 = kt * 8 + c;        // W2r row
            int row1 = row0 + 4;          // -W2i row
            ub0[kt] = __float_as_uint(Bs[row0 * 32 + (j2col ^ (row0 & 31))]);
            ub1[kt] = __float_as_uint(Bs[row1 * 32 + (j2col ^ (row1 & 31))]);
        }
    }

    // ---------- Main loop: 16 kt x 4 mt, ONE mma each, zero cvt ----------
    float d0[4], d1[4], d2[4], d3[4];
#pragma unroll
    for (int mt = 0; mt < 4; mt++) { d0[mt] = 0.f; d1[mt] = 0.f; d2[mt] = 0.f; d3[mt] = 0.f; }

    const float2* Ap = (const float2*)As;
#pragma unroll
    for (int kt = 0; kt < 16; kt++) {
#pragma unroll
        for (int mt = 0; mt < 4; mt++) {
            // (W1r, W1i) of n = 4kt + c at rows r and r+8 (already tf32-rounded).
            float2 a01 = Ap[kt * 256 + (mt * 16 + r) * 4 + c];
            float2 a23 = Ap[kt * 256 + (mt * 16 + 8 + r) * 4 + c];
            uint32_t ua0 = __float_as_uint(a01.x);   // (r,   c)
            uint32_t ua1 = __float_as_uint(a23.x);   // (r+8, c)
            uint32_t ua2 = __float_as_uint(a01.y);   // (r,   c+4)
            uint32_t ua3 = __float_as_uint(a23.y);   // (r+8, c+4)
            asm("mma.sync.aligned.m16n8k8.row.col.f32.tf32.tf32.f32 "
                "{%0,%1,%2,%3}, {%4,%5,%6,%7}, {%8,%9}, {%0,%1,%2,%3};"
                : "+f"(d0[mt]), "+f"(d1[mt]), "+f"(d2[mt]), "+f"(d3[mt])
                : "r"(ua0), "r"(ua1), "r"(ua2), "r"(ua3),
                  "r"(ub0[kt]), "r"(ub1[kt]));
        }
    }

    // ---------- Epilogue: C frag -> out[h, j1 + 64*j2] ----------
    float* o = out + h * LL;
    int j2a = 8 * w + 2 * c;
#pragma unroll
    for (int mt = 0; mt < 4; mt++) {
        int row = mt * 16 + r;
        o[row     + 64 * j2a]       = d0[mt];
        o[row     + 64 * (j2a + 1)] = d1[mt];
        o[row + 8 + 64 * j2a]       = d2[mt];
        o[row + 8 + 64 * (j2a + 1)] = d3[mt];
    }
}

extern "C" void kernel_launch(void* const* d_in, const int* in_sizes, int n_in,
                              void* d_out, int out_size) {
    const float* A_real = (const float*)d_in[0];
    const float* A_imag = (const float*)d_in[1];
    const float* B      = (const float*)d_in[2];
    const float* C      = (const float*)d_in[3];
    const float* inv_dt = (const float*)d_in[4];
    float* out = (float*)d_out;

    s4d_all<<<HH, 32 * NWARP>>>(A_real, A_imag, B, C, inv_dt, out);
}